// round 16
// baseline (speedup 1.0000x reference)
#include <cuda_runtime.h>
#include <cstdint>

#define Hh 192
#define Ww 192
#define HW 36864
#define NPIX 147456
#define INC 256
#define HID 16
#define MIDC 288
#define OUTC 128
#define PS 148           // attn exchange per-pixel stride (floats): phase-conflict-free f4
#define KS 136           // k_out smem row stride (words), ==8 mod 32
#define TPS 808          // proj tile plane stride (words: 10 rows x 80 + 8), ==8 mod 32

// Scratch (device globals: allocation-free per harness rules)
__device__ float4 g_h4[2][4][NPIX];      // (branch, ch-chunk, pixel) plane-major ~18.9 MB
__device__ float  g_midT[NPIX][MIDC];    // pixel-major (K-contiguous for MMA B) ~162 MB

// group -> spatial offset (unit steps; multiplied by shift). g==8 is center (+h).
__constant__ int c_oy[9] = {-1,-1,-1, 0, 1, 1, 1, 0, 0};
__constant__ int c_ox[9] = {-1, 0, 1, 1, 1, 0,-1,-1, 0};

__device__ __forceinline__ uint32_t f2tf32(float v) {
    uint32_t u;
    asm("cvt.rna.tf32.f32 %0, %1;" : "=r"(u) : "f"(v));
    return u;
}
#define MMA_TF32(acc, a, b)                                                        \
    asm volatile("mma.sync.aligned.m16n8k8.row.col.f32.tf32.tf32.f32 "             \
                 "{%0,%1,%2,%3}, {%4,%5,%6,%7}, {%8,%9}, {%0,%1,%2,%3};"           \
                 : "+f"(acc[0]), "+f"(acc[1]), "+f"(acc[2]), "+f"(acc[3])          \
                 : "r"(a[0]), "r"(a[1]), "r"(a[2]), "r"(a[3]), "r"(b[0]), "r"(b[1]))

// ---------------------------------------------------------------------------
// Kernel 1 (merged, mma.sync tf32): h1 = conv3x3(cen,W1)+b1 AND h0 = W0*cen+b0
// as ONE GEMM: M=32 (16 h1-ch + 16 h0-ch), N=64 px/warp, K=2304 (tap x ch),
// h0 rows have nonzero weights only at the center tap.
// Block: 256 thr / 8 warps; warp w = output row y0+w. Grid (3, 24, 4).
// tile: tf32 bits [16ch][10r][80c] plane stride TPS=808 (==8 mod 32);
// sA: [144k][40] (==8 mod 32). Both conflict-free for fragment LDS.
// ---------------------------------------------------------------------------
__global__ void __launch_bounds__(256) k_proj_mma(const float* __restrict__ cen,
                                                  const float* __restrict__ w1,
                                                  const float* __restrict__ b1f,
                                                  const float* __restrict__ w0,
                                                  const float* __restrict__ b0f) {
    extern __shared__ uint32_t smp[];
    uint32_t* tile = smp;               // 16 * TPS = 12928 words
    uint32_t* sA   = smp + 16 * TPS;    // 144 * 40 = 5760 words

    int tid = threadIdx.x;
    int w = tid >> 5, lane = tid & 31;
    int r = lane >> 2, c = lane & 3;
    int x0 = blockIdx.x * 64, y0 = blockIdx.y * 8, bi = blockIdx.z;

    float acc[2][8][4];
#pragma unroll
    for (int mt = 0; mt < 2; mt++)
#pragma unroll
        for (int nt = 0; nt < 8; nt++)
#pragma unroll
            for (int j = 0; j < 4; j++) acc[mt][nt][j] = 0.f;

    for (int s = 0; s < 16; s++) {
        int cc0 = s * 16;
        __syncthreads();
        // ---- stage input tile interior (float4, warp-uniform predicates)
        {
            int cc = tid >> 4, f4 = tid & 15;
            const float* src = cen + (size_t)(bi * INC + cc0 + cc) * HW + x0 + f4 * 4;
            uint32_t* dst = tile + cc * TPS + 4 + f4 * 4;
#pragma unroll
            for (int rr = 0; rr < 10; rr++) {
                int y = y0 - 1 + rr;
                float4 v = make_float4(0.f, 0.f, 0.f, 0.f);
                if ((unsigned)y < Hh) v = __ldg((const float4*)(src + (size_t)y * Ww));
                uint4 u = make_uint4(f2tf32(v.x), f2tf32(v.y), f2tf32(v.z), f2tf32(v.w));
                *(uint4*)(dst + rr * 80) = u;
            }
        }
        // ---- halo columns (2 per row per channel)
        for (int t = tid; t < 320; t += 256) {
            int cc = t / 20, rem = t - cc * 20, rr = rem >> 1, side = rem & 1;
            int y = y0 - 1 + rr;
            int x = side ? x0 + 64 : x0 - 1;
            float v = 0.f;
            if ((unsigned)y < Hh && (unsigned)x < Ww)
                v = __ldg(cen + (size_t)(bi * INC + cc0 + cc) * HW + y * Ww + x);
            tile[cc * TPS + rr * 80 + (side ? 68 : 3)] = f2tf32(v);
        }
        // ---- stage A, h1 half (m 0..15): coalesced float4 over (ch,tap) runs
        for (int t = tid; t < 576; t += 256) {
            int m = t / 36, q = t - m * 36;
            float4 v = __ldg((const float4*)(w1 + (size_t)m * 2304 + cc0 * 9 + q * 4));
            float vv[4] = {v.x, v.y, v.z, v.w};
#pragma unroll
            for (int u = 0; u < 4; u++) {
                int li = q * 4 + u;
                int cc = li / 9, tap = li - cc * 9;
                sA[(tap * 16 + cc) * 40 + m] = f2tf32(vv[u]);
            }
        }
        // ---- stage A, h0 half (m 16..31): center tap only, zeros elsewhere
        for (int t = tid; t < 2304; t += 256) {
            int kidx = t >> 4, m2 = t & 15;
            int tap = kidx >> 4, cc = kidx & 15;
            float v = (tap == 4) ? __ldg(w0 + m2 * INC + cc0 + cc) : 0.f;
            sA[kidx * 40 + 16 + m2] = f2tf32(v);
        }
        __syncthreads();

        // ---- 18 k8-steps: pure LDS + MMA (data already tf32)
#pragma unroll
        for (int kstep = 0; kstep < 18; kstep++) {
            const int tap = kstep >> 1, cg = kstep & 1;
            const int dy = tap / 3, dx = tap - dy * 3;
            int k8 = kstep * 8;
            uint32_t a0[4], a1[4];
            a0[0] = sA[(k8 + c) * 40 + r];          a0[1] = sA[(k8 + c) * 40 + r + 8];
            a0[2] = sA[(k8 + c + 4) * 40 + r];      a0[3] = sA[(k8 + c + 4) * 40 + r + 8];
            a1[0] = sA[(k8 + c) * 40 + 16 + r];     a1[1] = sA[(k8 + c) * 40 + 24 + r];
            a1[2] = sA[(k8 + c + 4) * 40 + 16 + r]; a1[3] = sA[(k8 + c + 4) * 40 + 24 + r];
            const uint32_t* base0 = tile + (cg * 8 + c) * TPS + (w + dy) * 80 + r + dx + 3;
            const uint32_t* base1 = base0 + 4 * TPS;
#pragma unroll
            for (int nt = 0; nt < 8; nt++) {
                uint32_t bf[2];
                bf[0] = base0[nt * 8];
                bf[1] = base1[nt * 8];
                MMA_TF32(acc[0][nt], a0, bf);
                MMA_TF32(acc[1][nt], a1, bf);
            }
        }
    }

    // ---- epilogue: bias, smem transpose (reuse tile+sA region), f4 stores
    float bs1a = __ldg(b1f + r), bs1b = __ldg(b1f + r + 8);
    float bs0a = __ldg(b0f + r), bs0b = __ldg(b0f + r + 8);
    __syncthreads();
    float* outs = (float*)smp + w * 2176;          // per-warp 2 x [16][68]
#pragma unroll
    for (int nt = 0; nt < 8; nt++) {
        int px = nt * 8 + 2 * c;
        outs[r * 68 + px]           = acc[0][nt][0] + bs1a;
        outs[r * 68 + px + 1]       = acc[0][nt][1] + bs1a;
        outs[(r + 8) * 68 + px]     = acc[0][nt][2] + bs1b;
        outs[(r + 8) * 68 + px + 1] = acc[0][nt][3] + bs1b;
        float* o2 = outs + 1088;
        o2[r * 68 + px]           = acc[1][nt][0] + bs0a;
        o2[r * 68 + px + 1]       = acc[1][nt][1] + bs0a;
        o2[(r + 8) * 68 + px]     = acc[1][nt][2] + bs0b;
        o2[(r + 8) * 68 + px + 1] = acc[1][nt][3] + bs0b;
    }
    __syncwarp();
    int prow = bi * HW + (y0 + w) * Ww + x0;
#pragma unroll
    for (int i = 0; i < 8; i++) {
        int idx = i * 32 + lane;
        int px = idx & 63, j = idx >> 6;
        g_h4[1][j][prow + px] = make_float4(outs[(4*j+0) * 68 + px],
                                            outs[(4*j+1) * 68 + px],
                                            outs[(4*j+2) * 68 + px],
                                            outs[(4*j+3) * 68 + px]);
        const float* o2 = outs + 1088;
        g_h4[0][j][prow + px] = make_float4(o2[(4*j+0) * 68 + px],
                                            o2[(4*j+1) * 68 + px],
                                            o2[(4*j+2) * 68 + px],
                                            o2[(4*j+3) * 68 + px]);
    }
}

// ---------------------------------------------------------------------------
// Kernel 2: per-pixel group attention. Warp = group g, lane = pixel.
// o1/o3 exchange per-pixel contiguous [pl][PS=148]: float4, phase-conflict-free.
// ---------------------------------------------------------------------------
__global__ void __launch_bounds__(288) k_attn(const float* __restrict__ w1,
                                              const float* __restrict__ w2,
                                              const float* __restrict__ w3,
                                              const float* __restrict__ scl,
                                              int br, int shift) {
    extern __shared__ float sm[];
    float* W1s = sm;                 // [9][16(c)][16(d)]
    float* W2s = sm + 2304;
    float* W3s = sm + 4608;
    float* o1s = sm + 6912;          // [32][PS]
    float* o3s = o1s + 32 * PS;

    for (int t = threadIdx.x; t < 2304; t += 288) {
        int g = t >> 8; int rem = t & 255; int c = rem >> 4; int d = rem & 15;
        int src = (g * 16 + d) * 16 + c;       // weights are (9, d, c)
        W1s[t] = __ldg(w1 + src);
        W2s[t] = __ldg(w2 + src);
        W3s[t] = __ldg(w3 + src);
    }
    __syncthreads();

    int g  = threadIdx.x >> 5;                 // warp id == group (0..8)
    int pl = threadIdx.x & 31;                 // lane == pixel within block
    int p  = blockIdx.x * 32 + pl;             // 4608 blocks * 32 == NPIX
    int b = p / HW, r = p - b * HW, y = r / Ww, x = r - y * Ww;

    int yy = y + c_oy[g] * shift, xx = x + c_ox[g] * shift;
    bool valid = ((unsigned)yy < Hh) && ((unsigned)xx < Ww);
    float sign = (g == 8) ? 1.f : -1.f;
    int sidx = valid ? (b * HW + yy * Ww + xx) : 0;

    float v[16];
#pragma unroll
    for (int j = 0; j < 4; j++) {
        float4 t = g_h4[br][j][sidx];
        if (!valid) t = make_float4(0.f, 0.f, 0.f, 0.f);
        v[4*j+0] = sign * t.x; v[4*j+1] = sign * t.y;
        v[4*j+2] = sign * t.z; v[4*j+3] = sign * t.w;
    }

    float o[16];
    // ---- o1 -> smem exchange
#pragma unroll
    for (int j = 0; j < 16; j++) o[j] = 0.f;
    {
        const float* Wg = W1s + g * 256;
#pragma unroll
        for (int c = 0; c < 16; c++) {
            float vc = v[c];
            const float4* w4 = (const float4*)(Wg + c * 16);
#pragma unroll
            for (int j = 0; j < 4; j++) {
                float4 w = w4[j];
                o[4*j+0] = fmaf(w.x, vc, o[4*j+0]);
                o[4*j+1] = fmaf(w.y, vc, o[4*j+1]);
                o[4*j+2] = fmaf(w.z, vc, o[4*j+2]);
                o[4*j+3] = fmaf(w.w, vc, o[4*j+3]);
            }
        }
    }
    {
        float4* dst = (float4*)(o1s + pl * PS + g * 16);
#pragma unroll
        for (int j = 0; j < 4; j++)
            dst[j] = make_float4(o[4*j], o[4*j+1], o[4*j+2], o[4*j+3]);
    }
    // ---- o3 -> smem exchange
#pragma unroll
    for (int j = 0; j < 16; j++) o[j] = 0.f;
    {
        const float* Wg = W3s + g * 256;
#pragma unroll
        for (int c = 0; c < 16; c++) {
            float vc = v[c];
            const float4* w4 = (const float4*)(Wg + c * 16);
#pragma unroll
            for (int j = 0; j < 4; j++) {
                float4 w = w4[j];
                o[4*j+0] = fmaf(w.x, vc, o[4*j+0]);
                o[4*j+1] = fmaf(w.y, vc, o[4*j+1]);
                o[4*j+2] = fmaf(w.z, vc, o[4*j+2]);
                o[4*j+3] = fmaf(w.w, vc, o[4*j+3]);
            }
        }
    }
    {
        float4* dst = (float4*)(o3s + pl * PS + g * 16);
#pragma unroll
        for (int j = 0; j < 4; j++)
            dst[j] = make_float4(o[4*j], o[4*j+1], o[4*j+2], o[4*j+3]);
    }
    // ---- o2 stays in regs
#pragma unroll
    for (int j = 0; j < 16; j++) o[j] = 0.f;
    {
        const float* Wg = W2s + g * 256;
#pragma unroll
        for (int c = 0; c < 16; c++) {
            float vc = v[c];
            const float4* w4 = (const float4*)(Wg + c * 16);
#pragma unroll
            for (int j = 0; j < 4; j++) {
                float4 w = w4[j];
                o[4*j+0] = fmaf(w.x, vc, o[4*j+0]);
                o[4*j+1] = fmaf(w.y, vc, o[4*j+1]);
                o[4*j+2] = fmaf(w.z, vc, o[4*j+2]);
                o[4*j+3] = fmaf(w.w, vc, o[4*j+3]);
            }
        }
    }
    __syncthreads();

    float sc = __ldg(scl + br);
    float l[9];
    const float* basep = o1s + pl * PS;
#pragma unroll
    for (int q = 0; q < 9; q++) {
        const float4* oq = (const float4*)(basep + q * 16);
        float s = 0.f;
#pragma unroll
        for (int j = 0; j < 4; j++) {
            float4 t = oq[j];
            s = fmaf(o[4*j+0], t.x, s);
            s = fmaf(o[4*j+1], t.y, s);
            s = fmaf(o[4*j+2], t.z, s);
            s = fmaf(o[4*j+3], t.w, s);
        }
        l[q] = s * sc;
    }
    float m = l[0];
#pragma unroll
    for (int q = 1; q < 9; q++) m = fmaxf(m, l[q]);
    float ssum = 0.f;
#pragma unroll
    for (int q = 0; q < 9; q++) { l[q] = __expf(l[q] - m); ssum += l[q]; }
    float inv = 1.f / ssum;

    float outv[16];
#pragma unroll
    for (int j = 0; j < 16; j++) outv[j] = 0.f;
    const float* b3 = o3s + pl * PS;
#pragma unroll
    for (int q = 0; q < 9; q++) {
        float a = l[q] * inv;
        const float4* oq = (const float4*)(b3 + q * 16);
#pragma unroll
        for (int j = 0; j < 4; j++) {
            float4 t = oq[j];
            outv[4*j+0] = fmaf(a, t.x, outv[4*j+0]);
            outv[4*j+1] = fmaf(a, t.y, outv[4*j+1]);
            outv[4*j+2] = fmaf(a, t.z, outv[4*j+2]);
            outv[4*j+3] = fmaf(a, t.w, outv[4*j+3]);
        }
    }
    // pixel-major store (K-contiguous for the MMA B operand)
    float4* mp = (float4*)(g_midT[p] + br * 144 + g * 16);
#pragma unroll
    for (int j = 0; j < 4; j++)
        mp[j] = make_float4(outv[4*j], outv[4*j+1], outv[4*j+2], outv[4*j+3]);
}

// ---------------------------------------------------------------------------
// Kernel 3 (mma.sync tf32): out[128ch, 128pix/block] = W[128,288] . midT^T
// ---------------------------------------------------------------------------
__global__ void __launch_bounds__(256) k_out_mma(const float* __restrict__ ow,
                                                 const float* __restrict__ ob,
                                                 float* __restrict__ out) {
    __shared__ uint32_t sA[32 * KS];   // [k][ch]  tf32 bits
    __shared__ uint32_t sB[32 * KS];   // [k][pix] tf32 bits

    int tid = threadIdx.x;
    int wid = tid >> 5, lane = tid & 31;
    int r = lane >> 2, c = lane & 3;
    int chbase = (wid & 1) * 64;
    int pixbase = (wid >> 1) * 32;
    int p0 = blockIdx.x * 128;                 // 1152 blocks; never straddles batch
    int b = p0 / HW, r0 = p0 - b * HW;

    float acc[4][4][4];
#pragma unroll
    for (int mt = 0; mt < 4; mt++)
#pragma unroll
        for (int nt = 0; nt < 4; nt++)
#pragma unroll
            for (int j = 0; j < 4; j++) acc[mt][nt][j] = 0.f;

    for (int ch = 0; ch < 9; ch++) {           // K chunks of 32
        __syncthreads();
#pragma unroll
        for (int t = tid; t < 1024; t += 256) {
            int row = t >> 3, f4 = t & 7;      // row: 0..127, f4: 0..7
            float4 wv = __ldg((const float4*)(ow + (size_t)row * MIDC + ch * 32 + f4 * 4));
            sA[(f4 * 4 + 0) * KS + row] = f2tf32(wv.x);
            sA[(f4 * 4 + 1) * KS + row] = f2tf32(wv.y);
            sA[(f4 * 4 + 2) * KS + row] = f2tf32(wv.z);
            sA[(f4 * 4 + 3) * KS + row] = f2tf32(wv.w);
            float4 mv = *(const float4*)(g_midT[p0 + row] + ch * 32 + f4 * 4);
            sB[(f4 * 4 + 0) * KS + row] = f2tf32(mv.x);
            sB[(f4 * 4 + 1) * KS + row] = f2tf32(mv.y);
            sB[(f4 * 4 + 2) * KS + row] = f2tf32(mv.z);
            sB[(f4 * 4 + 3) * KS + row] = f2tf32(mv.w);
        }
        __syncthreads();

#pragma unroll
        for (int ks = 0; ks < 4; ks++) {
            int k = ks * 8;
            uint32_t a[4][4];
#pragma unroll
            for (int mt = 0; mt < 4; mt++) {
                int chh = chbase + mt * 16 + r;
                a[mt][0] = sA[(k + c) * KS + chh];
                a[mt][1] = sA[(k + c) * KS + chh + 8];
                a[mt][2] = sA[(k + c + 4) * KS + chh];
                a[mt][3] = sA[(k + c + 4) * KS + chh + 8];
            }
            uint32_t bf[4][2];
#pragma unroll
            for (int nt = 0; nt < 4; nt++) {
                int px = pixbase + nt * 8 + r;
                bf[nt][0] = sB[(k + c) * KS + px];
                bf[nt][1] = sB[(k + c + 4) * KS + px];
            }
#pragma unroll
            for (int mt = 0; mt < 4; mt++)
#pragma unroll
                for (int nt = 0; nt < 4; nt++)
                    MMA_TF32(acc[mt][nt], a[mt], bf[nt]);
        }
    }

    // Epilogue: add bias, store. c0/c1 -> (ch0, pix 2c..2c+1); c2/c3 -> ch0+8.
#pragma unroll
    for (int mt = 0; mt < 4; mt++) {
        int ch0 = chbase + mt * 16 + r;
        float bias0 = __ldg(ob + ch0);
        float bias1 = __ldg(ob + ch0 + 8);
        float* row0 = out + ((size_t)b * OUTC + ch0) * HW + r0;
#pragma unroll
        for (int nt = 0; nt < 4; nt++) {
            int pix = pixbase + nt * 8 + 2 * c;
            float2 v0 = make_float2(acc[mt][nt][0] + bias0, acc[mt][nt][1] + bias0);
            float2 v1 = make_float2(acc[mt][nt][2] + bias1, acc[mt][nt][3] + bias1);
            *(float2*)(row0 + pix) = v0;
            *(float2*)(row0 + (size_t)8 * HW + pix) = v1;
        }
    }
}

// ---------------------------------------------------------------------------
extern "C" void kernel_launch(void* const* d_in, const int* in_sizes, int n_in,
                              void* d_out, int out_size) {
    const float* cen   = (const float*)d_in[0];
    const float* in_w0 = (const float*)d_in[1];
    const float* in_b0 = (const float*)d_in[2];
    const float* in_w1 = (const float*)d_in[3];
    const float* in_b1 = (const float*)d_in[4];
    const float* w1_0  = (const float*)d_in[5];
    const float* w2_0  = (const float*)d_in[6];
    const float* w3_0  = (const float*)d_in[7];
    const float* w1_1  = (const float*)d_in[8];
    const float* w2_1  = (const float*)d_in[9];
    const float* w3_1  = (const float*)d_in[10];
    const float* scale = (const float*)d_in[11];
    const float* out_w = (const float*)d_in[12];
    const float* out_b = (const float*)d_in[13];
    float* out = (float*)d_out;

    const int attnSmem = (6912 + 2 * 32 * PS) * (int)sizeof(float);       // 65536 B
    const int projSmem = (16 * TPS + 144 * 40) * (int)sizeof(uint32_t);   // 74752 B
    cudaFuncSetAttribute(k_attn, cudaFuncAttributeMaxDynamicSharedMemorySize, attnSmem);
    cudaFuncSetAttribute(k_proj_mma, cudaFuncAttributeMaxDynamicSharedMemorySize, projSmem);

    k_proj_mma<<<dim3(3, 24, 4), 256, projSmem>>>(cen, in_w1, in_b1, in_w0, in_b0);
    k_attn<<<NPIX / 32, 288, attnSmem>>>(w1_0, w2_0, w3_0, scale, 0, 1);
    k_attn<<<NPIX / 32, 288, attnSmem>>>(w1_1, w2_1, w3_1, scale, 1, 5);
    k_out_mma<<<NPIX / 128, 256>>>(out_w, out_b, out);
}